// round 1
// baseline (speedup 1.0000x reference)
#include <cuda_runtime.h>
#include <math.h>

#define BSZ 2
#define SEQ 4096
#define DIM 512
#define NH  8
#define HDIM 64

// Scratch (no cudaMalloc allowed): 4 x 16 MB
__device__ float g_Q[BSZ*NH*SEQ*HDIM];
__device__ float g_K[BSZ*NH*SEQ*HDIM];
__device__ float g_V[BSZ*NH*SEQ*HDIM];
__device__ float g_Y[BSZ*SEQ*DIM];

// ---------------------------------------------------------------------------
// GEMM: C[M,N] = A[M,K] @ W[N,K]^T + bias[N]
// MODE 0: plain store to C.  MODE 1: scatter QKV into g_Q/g_K/g_V [B,H,S,HD].
// Block: 256 threads, 64x64 tile, BK=16, 4x4 register microtile per thread.
// ---------------------------------------------------------------------------
template<int MODE>
__global__ void gemm_bias_kernel(const float* __restrict__ A,
                                 const float* __restrict__ W,
                                 const float* __restrict__ bias,
                                 float* __restrict__ C,
                                 int M, int N, int K)
{
    __shared__ float As[64][16];   // [m][k] — reads are warp-broadcast
    __shared__ float Bs[16][65];   // [k][n] — pad makes transpose store conflict-free

    const int tid = threadIdx.x;
    const int tx = tid & 15;       // 0..15 -> n microtile
    const int ty = tid >> 4;       // 0..15 -> m microtile
    const int m0 = blockIdx.y * 64;
    const int n0 = blockIdx.x * 64;

    float acc[4][4] = {};

    for (int k0 = 0; k0 < K; k0 += 16) {
        #pragma unroll
        for (int i = 0; i < 4; i++) {
            int idx = tid + i * 256;       // 0..1023
            int r = idx >> 4;              // 0..63
            int c = idx & 15;              // 0..15
            As[r][c] = A[(m0 + r) * K + k0 + c];
            Bs[c][r] = W[(n0 + r) * K + k0 + c];
        }
        __syncthreads();

        #pragma unroll
        for (int kk = 0; kk < 16; kk++) {
            float a[4], b[4];
            #pragma unroll
            for (int i = 0; i < 4; i++) a[i] = As[ty * 4 + i][kk];
            #pragma unroll
            for (int j = 0; j < 4; j++) b[j] = Bs[kk][tx * 4 + j];
            #pragma unroll
            for (int i = 0; i < 4; i++)
                #pragma unroll
                for (int j = 0; j < 4; j++)
                    acc[i][j] += a[i] * b[j];
        }
        __syncthreads();
    }

    #pragma unroll
    for (int i = 0; i < 4; i++) {
        int m = m0 + ty * 4 + i;
        #pragma unroll
        for (int j = 0; j < 4; j++) {
            int n = n0 + tx * 4 + j;
            float v = acc[i][j] + bias[n];
            if (MODE == 0) {
                C[m * N + n] = v;
            } else {
                // n in [0,1536): which 512-chunk, then head, then hd
                int which = n >> 9;
                int h = (n >> 6) & 7;
                int d = n & 63;
                int b = m >> 12;        // m / 4096
                int s = m & 4095;
                float* dst = (which == 0) ? g_Q : (which == 1) ? g_K : g_V;
                dst[(((b * NH + h) * SEQ) + s) * HDIM + d] = v;
            }
        }
    }
}

// ---------------------------------------------------------------------------
// Causal flash attention.
// grid = (SEQ/64, NH, BSZ), block = 256 threads.
// Q tile: 64 rows x 64 hd.  KV tile: 32 rows.
// Thread (tx,ty): owns q-rows ty*4..ty*4+3.
//   scores: cols tx*2, tx*2+1 (64x32 / 256 threads)
//   output: hd cols tx*4..tx*4+3 (64x64 / 256 threads)
// Row softmax stats kept in registers, replicated across the 16 tx threads
// of a row via shfl_xor reductions (lanes 0-15 / 16-31 are separate rows).
// ---------------------------------------------------------------------------
__global__ void flash_attn_kernel()
{
    __shared__ float Qs[64][64];    // broadcast reads, no pad needed
    __shared__ float Ks[32][65];    // pad: score reads stride-2 -> conflict free
    __shared__ float Vs[32][64];    // read via float4 (LDS.128)
    __shared__ float Ps[64][33];    // probabilities staged for P@V

    const int qt = blockIdx.x;
    const int h  = blockIdx.y;
    const int b  = blockIdx.z;
    const int tid = threadIdx.x;
    const int tx = tid & 15;
    const int ty = tid >> 4;

    const float* Qb = g_Q + ((size_t)(b * NH + h) * SEQ + qt * 64) * HDIM;
    const float* Kb = g_K + (size_t)(b * NH + h) * SEQ * HDIM;
    const float* Vb = g_V + (size_t)(b * NH + h) * SEQ * HDIM;

    // Load Q tile (4096 floats) as float4
    #pragma unroll
    for (int i = 0; i < 4; i++) {
        int idx = tid + i * 256;        // float4 index, 0..1023
        int r = idx >> 4, c4 = idx & 15;
        *(float4*)&Qs[r][c4 * 4] = *(const float4*)&Qb[r * 64 + c4 * 4];
    }

    float m_i[4], l_i[4], o[4][4];
    #pragma unroll
    for (int i = 0; i < 4; i++) {
        m_i[i] = -1e30f; l_i[i] = 0.f;
        #pragma unroll
        for (int c = 0; c < 4; c++) o[i][c] = 0.f;
    }

    const int nkt = 2 * qt + 2;   // 32-wide kv tiles covering [0, qt*64+64)

    for (int kt = 0; kt < nkt; kt++) {
        const int kv0 = kt * 32;
        __syncthreads();  // previous-iteration smem consumers done (also covers Q load on iter 0... Q is read-only, fine)

        // Load K tile: scalar (Ks padded), 2048 elems, 8 per thread, coalesced
        #pragma unroll
        for (int i = 0; i < 8; i++) {
            int idx = tid + i * 256;     // 0..2047
            int r = idx >> 6, c = idx & 63;
            Ks[r][c] = Kb[(size_t)(kv0 + r) * 64 + c];
        }
        // Load V tile: float4, 512 vecs, 2 per thread
        #pragma unroll
        for (int i = 0; i < 2; i++) {
            int idx = tid + i * 256;
            int r = idx >> 4, c4 = idx & 15;
            *(float4*)&Vs[r][c4 * 4] = *(const float4*)&Vb[(size_t)(kv0 + r) * 64 + c4 * 4];
        }
        __syncthreads();

        // S = Q @ K^T  (scaled)
        float s[4][2] = {};
        #pragma unroll
        for (int kk = 0; kk < 64; kk++) {
            float a[4], bv[2];
            #pragma unroll
            for (int i = 0; i < 4; i++) a[i] = Qs[ty * 4 + i][kk];
            #pragma unroll
            for (int j = 0; j < 2; j++) bv[j] = Ks[tx * 2 + j][kk];
            #pragma unroll
            for (int i = 0; i < 4; i++)
                #pragma unroll
                for (int j = 0; j < 2; j++)
                    s[i][j] += a[i] * bv[j];
        }

        const bool diag = (kv0 + 31 > qt * 64);  // tile can cross the diagonal
        #pragma unroll
        for (int i = 0; i < 4; i++) {
            int rowg = qt * 64 + ty * 4 + i;
            #pragma unroll
            for (int j = 0; j < 2; j++) {
                s[i][j] *= 0.125f;               // 1/sqrt(64)
                if (diag) {
                    int colg = kv0 + tx * 2 + j;
                    if (colg > rowg) s[i][j] = -1e30f;
                }
            }
        }

        // Online softmax update (per q-row, reduced across the 16 tx lanes)
        #pragma unroll
        for (int i = 0; i < 4; i++) {
            float mloc = fmaxf(s[i][0], s[i][1]);
            #pragma unroll
            for (int off = 8; off >= 1; off >>= 1)
                mloc = fmaxf(mloc, __shfl_xor_sync(0xffffffffu, mloc, off));
            float mnew = fmaxf(m_i[i], mloc);
            float p0 = __expf(s[i][0] - mnew);
            float p1 = __expf(s[i][1] - mnew);
            float sloc = p0 + p1;
            #pragma unroll
            for (int off = 8; off >= 1; off >>= 1)
                sloc += __shfl_xor_sync(0xffffffffu, sloc, off);
            float corr = __expf(m_i[i] - mnew);
            l_i[i] = l_i[i] * corr + sloc;
            #pragma unroll
            for (int c = 0; c < 4; c++) o[i][c] *= corr;
            m_i[i] = mnew;
            Ps[ty * 4 + i][tx * 2 + 0] = p0;
            Ps[ty * 4 + i][tx * 2 + 1] = p1;
        }
        __syncthreads();

        // O += P @ V
        #pragma unroll
        for (int jj = 0; jj < 32; jj++) {
            float4 v4 = *(float4*)&Vs[jj][tx * 4];
            #pragma unroll
            for (int i = 0; i < 4; i++) {
                float p = Ps[ty * 4 + i][jj];
                o[i][0] += p * v4.x;
                o[i][1] += p * v4.y;
                o[i][2] += p * v4.z;
                o[i][3] += p * v4.w;
            }
        }
    }

    // Epilogue: normalize and write [B,S,D] with head offset
    float* Yb = g_Y + ((size_t)b * SEQ + qt * 64) * DIM + h * HDIM;
    #pragma unroll
    for (int i = 0; i < 4; i++) {
        float inv = 1.0f / l_i[i];
        #pragma unroll
        for (int c = 0; c < 4; c++)
            Yb[(ty * 4 + i) * DIM + tx * 4 + c] = o[i][c] * inv;
    }
}

// ---------------------------------------------------------------------------
extern "C" void kernel_launch(void* const* d_in, const int* in_sizes, int n_in,
                              void* d_out, int out_size)
{
    const float* x    = (const float*)d_in[0];   // [2,4096,512]
    const float* Wqkv = (const float*)d_in[1];   // [1536,512]
    const float* bqkv = (const float*)d_in[2];   // [1536]
    const float* Wo   = (const float*)d_in[3];   // [512,512]
    const float* bo   = (const float*)d_in[4];   // [512]
    float* out = (float*)d_out;                  // [2,4096,512]

    void* yptr = nullptr;
    cudaGetSymbolAddress(&yptr, g_Y);

    const int M = BSZ * SEQ;     // 8192

    // 1) QKV projection, scattered into g_Q/g_K/g_V
    {
        dim3 grid((3 * DIM) / 64, M / 64);
        gemm_bias_kernel<1><<<grid, 256>>>(x, Wqkv, bqkv, nullptr, M, 3 * DIM, DIM);
    }
    // 2) Causal flash attention -> g_Y [B,S,D]
    {
        dim3 grid(SEQ / 64, NH, BSZ);
        flash_attn_kernel<<<grid, 256>>>();
    }
    // 3) Output projection
    {
        dim3 grid(DIM / 64, M / 64);
        gemm_bias_kernel<0><<<grid, 256>>>((const float*)yptr, Wo, bo, out, M, DIM, DIM);
    }
}

// round 10
// speedup vs baseline: 3.5443x; 3.5443x over previous
#include <cuda_runtime.h>
#include <cuda_bf16.h>
#include <cstdint>
#include <math.h>

#define BSZ 2
#define SEQ 4096
#define DIM 512
#define NH  8
#define HDIM 64
#define NELEM (BSZ*NH*SEQ*HDIM)

// Scratch (no cudaMalloc allowed). Q scaled by 1/8; V stored transposed [b,h,hd,s].
__device__ __nv_bfloat16 g_Qh[NELEM], g_Ql[NELEM];
__device__ __nv_bfloat16 g_Kh[NELEM], g_Kl[NELEM];
__device__ __nv_bfloat16 g_Vh[NELEM], g_Vl[NELEM];
__device__ float g_Y[BSZ*SEQ*DIM];

// ---------------------------------------------------------------------------
// Warp-MMA helpers (sm_80 baseline ISA — compiles at plain compute_103)
// ---------------------------------------------------------------------------
__device__ __forceinline__ void mma16816(float* c, const uint32_t* a, const uint32_t* b) {
    asm volatile(
        "mma.sync.aligned.m16n8k16.row.col.f32.bf16.bf16.f32 "
        "{%0,%1,%2,%3}, {%4,%5,%6,%7}, {%8,%9}, {%0,%1,%2,%3};"
        : "+f"(c[0]), "+f"(c[1]), "+f"(c[2]), "+f"(c[3])
        : "r"(a[0]), "r"(a[1]), "r"(a[2]), "r"(a[3]), "r"(b[0]), "r"(b[1]));
}

__device__ __forceinline__ void split2(float v, __nv_bfloat16& h, __nv_bfloat16& l) {
    h = __float2bfloat16(v);
    l = __float2bfloat16(v - __bfloat162float(h));
}
__device__ __forceinline__ void packsplit(float x, float y, uint32_t& hi, uint32_t& lo) {
    __nv_bfloat16 hx, lx, hy, ly;
    split2(x, hx, lx); split2(y, hy, ly);
    __nv_bfloat162 h2 = __halves2bfloat162(hx, hy);
    __nv_bfloat162 l2 = __halves2bfloat162(lx, ly);
    hi = *(uint32_t*)&h2; lo = *(uint32_t*)&l2;
}

// ---------------------------------------------------------------------------
// GEMM: C[M,N] = A[M,K] @ W[N,K]^T + bias.  bf16 hi/lo split, 3 MMA passes.
// Block 128x128, 256 threads (8 warps: 4m x 2n, warp tile 32x64), K-chunk 32.
// MODE 0: fp32 store to C.   MODE 1: QKV split-bf16 scatter.
// ---------------------------------------------------------------------------
#define GSTR 40   // smem row stride (elems): (20r+t)%32 all-distinct -> conflict-free

template<int MODE>
__launch_bounds__(256)
__global__ void gemm_mma(const float* __restrict__ A, const float* __restrict__ W,
                         const float* __restrict__ bias, float* __restrict__ C,
                         int M, int N, int K)
{
    __shared__ __nv_bfloat16 sAh[128][GSTR], sAl[128][GSTR];
    __shared__ __nv_bfloat16 sBh[128][GSTR], sBl[128][GSTR];

    const int tid = threadIdx.x;
    const int lane = tid & 31, wid = tid >> 5;
    const int gid = lane >> 2, tig = lane & 3;
    const int wm = (wid >> 1) * 32, wn = (wid & 1) * 64;
    const int m0 = blockIdx.y * 128, n0 = blockIdx.x * 128;

    float acc[2][8][4];
    #pragma unroll
    for (int mt = 0; mt < 2; mt++)
        #pragma unroll
        for (int nt = 0; nt < 8; nt++)
            #pragma unroll
            for (int q = 0; q < 4; q++) acc[mt][nt][q] = 0.f;

    for (int k0 = 0; k0 < K; k0 += 32) {
        // stage A and W chunk (128x32 fp32 each) as split bf16
        #pragma unroll
        for (int i = 0; i < 4; i++) {
            int idx = tid + i * 256;         // 0..1023 float4 slots
            int r = idx >> 3, c = (idx & 7) * 4;
            float4 fa = *(const float4*)&A[(size_t)(m0 + r) * K + k0 + c];
            __nv_bfloat16 h0,h1,h2,h3,l0,l1,l2,l3;
            split2(fa.x,h0,l0); split2(fa.y,h1,l1); split2(fa.z,h2,l2); split2(fa.w,h3,l3);
            *(__nv_bfloat162*)&sAh[r][c]   = __halves2bfloat162(h0,h1);
            *(__nv_bfloat162*)&sAh[r][c+2] = __halves2bfloat162(h2,h3);
            *(__nv_bfloat162*)&sAl[r][c]   = __halves2bfloat162(l0,l1);
            *(__nv_bfloat162*)&sAl[r][c+2] = __halves2bfloat162(l2,l3);
            float4 fw = *(const float4*)&W[(size_t)(n0 + r) * K + k0 + c];
            split2(fw.x,h0,l0); split2(fw.y,h1,l1); split2(fw.z,h2,l2); split2(fw.w,h3,l3);
            *(__nv_bfloat162*)&sBh[r][c]   = __halves2bfloat162(h0,h1);
            *(__nv_bfloat162*)&sBh[r][c+2] = __halves2bfloat162(h2,h3);
            *(__nv_bfloat162*)&sBl[r][c]   = __halves2bfloat162(l0,l1);
            *(__nv_bfloat162*)&sBl[r][c+2] = __halves2bfloat162(l2,l3);
        }
        __syncthreads();

        #pragma unroll
        for (int kk = 0; kk < 32; kk += 16) {
            uint32_t ah[2][4], al[2][4];
            #pragma unroll
            for (int mt = 0; mt < 2; mt++) {
                int r = wm + mt * 16 + gid;
                ah[mt][0] = *(uint32_t*)&sAh[r    ][kk + tig*2];
                ah[mt][1] = *(uint32_t*)&sAh[r + 8][kk + tig*2];
                ah[mt][2] = *(uint32_t*)&sAh[r    ][kk + tig*2 + 8];
                ah[mt][3] = *(uint32_t*)&sAh[r + 8][kk + tig*2 + 8];
                al[mt][0] = *(uint32_t*)&sAl[r    ][kk + tig*2];
                al[mt][1] = *(uint32_t*)&sAl[r + 8][kk + tig*2];
                al[mt][2] = *(uint32_t*)&sAl[r    ][kk + tig*2 + 8];
                al[mt][3] = *(uint32_t*)&sAl[r + 8][kk + tig*2 + 8];
            }
            uint32_t bh[8][2], bl[8][2];
            #pragma unroll
            for (int nt = 0; nt < 8; nt++) {
                int rn = wn + nt * 8 + gid;
                bh[nt][0] = *(uint32_t*)&sBh[rn][kk + tig*2];
                bh[nt][1] = *(uint32_t*)&sBh[rn][kk + tig*2 + 8];
                bl[nt][0] = *(uint32_t*)&sBl[rn][kk + tig*2];
                bl[nt][1] = *(uint32_t*)&sBl[rn][kk + tig*2 + 8];
            }
            #pragma unroll
            for (int mt = 0; mt < 2; mt++)
                #pragma unroll
                for (int nt = 0; nt < 8; nt++) {
                    mma16816(acc[mt][nt], ah[mt], bh[nt]);
                    mma16816(acc[mt][nt], ah[mt], bl[nt]);
                    mma16816(acc[mt][nt], al[mt], bh[nt]);
                }
        }
        __syncthreads();
    }

    // Epilogue
    #pragma unroll
    for (int mt = 0; mt < 2; mt++) {
        #pragma unroll
        for (int ih = 0; ih < 2; ih++) {
            int m = m0 + wm + mt * 16 + gid + ih * 8;
            #pragma unroll
            for (int nt = 0; nt < 8; nt++) {
                int n = n0 + wn + nt * 8 + tig * 2;
                float v0 = acc[mt][nt][ih*2 + 0] + __ldg(&bias[n]);
                float v1 = acc[mt][nt][ih*2 + 1] + __ldg(&bias[n + 1]);
                if (MODE == 0) {
                    float2 o2 = { v0, v1 };
                    *(float2*)&C[(size_t)m * N + n] = o2;
                } else {
                    int which = n >> 9, hh = (n >> 6) & 7, dd = n & 63;
                    int bb = m >> 12, s = m & 4095;
                    if (which == 0) {
                        size_t base = (((size_t)(bb * NH + hh) * SEQ) + s) * HDIM + dd;
                        uint32_t hi, lo;
                        packsplit(v0 * 0.125f, v1 * 0.125f, hi, lo);
                        *(uint32_t*)&g_Qh[base] = hi;
                        *(uint32_t*)&g_Ql[base] = lo;
                    } else if (which == 1) {
                        size_t base = (((size_t)(bb * NH + hh) * SEQ) + s) * HDIM + dd;
                        uint32_t hi, lo;
                        packsplit(v0, v1, hi, lo);
                        *(uint32_t*)&g_Kh[base] = hi;
                        *(uint32_t*)&g_Kl[base] = lo;
                    } else {
                        size_t base = ((size_t)(bb * NH + hh) * HDIM + dd) * SEQ + s;
                        __nv_bfloat16 h0, l0, h1, l1;
                        split2(v0, h0, l0); split2(v1, h1, l1);
                        g_Vh[base] = h0;       g_Vl[base] = l0;
                        g_Vh[base + SEQ] = h1; g_Vl[base + SEQ] = l1;
                    }
                }
            }
        }
    }
}

// ---------------------------------------------------------------------------
// Flash attention (warp MMA): Br=128, Bc=64, 4 warps / 128 threads.
// S = Q@K^T (3-pass split); softmax in registers (4-lane shfl reductions);
// P built from S accumulators (register pass-through, split); P@V 3-pass.
// ---------------------------------------------------------------------------
#define FSTR 72   // smem row stride (elems): (4r+t)%32 all-distinct -> conflict-free
#define QH_OFF 0
#define QL_OFF (128*FSTR*2)
#define KH_OFF (QL_OFF + 128*FSTR*2)
#define KL_OFF (KH_OFF + 64*FSTR*2)
#define VH_OFF (KL_OFF + 64*FSTR*2)
#define VL_OFF (VH_OFF + 64*FSTR*2)
#define FL_SMEM (VL_OFF + 64*FSTR*2)   // 73728 bytes

__launch_bounds__(128)
__global__ void flash_mma()
{
    extern __shared__ char smem[];
    __nv_bfloat16* QH = (__nv_bfloat16*)(smem + QH_OFF);
    __nv_bfloat16* QL = (__nv_bfloat16*)(smem + QL_OFF);
    __nv_bfloat16* KH = (__nv_bfloat16*)(smem + KH_OFF);
    __nv_bfloat16* KL = (__nv_bfloat16*)(smem + KL_OFF);
    __nv_bfloat16* VH = (__nv_bfloat16*)(smem + VH_OFF);
    __nv_bfloat16* VL = (__nv_bfloat16*)(smem + VL_OFF);

    const int tid = threadIdx.x;
    const int lane = tid & 31, wid = tid >> 5;
    const int gid = lane >> 2, tig = lane & 3;
    const int qt = (gridDim.x - 1) - blockIdx.x;   // heavy tiles first
    const int head = blockIdx.y;
    const int b = blockIdx.z;

    const size_t bh = (size_t)(b * NH + head);
    const __nv_bfloat16* Qhp = g_Qh + (bh * SEQ + qt * 128) * HDIM;
    const __nv_bfloat16* Qlp = g_Ql + (bh * SEQ + qt * 128) * HDIM;

    // Load Q tile (128x64 each buffer): uint4 = 8 bf16
    #pragma unroll
    for (int i = 0; i < 8; i++) {
        int idx = tid + i * 128;
        int r = idx >> 3, c = (idx & 7) * 8;
        *(uint4*)&QH[r * FSTR + c] = *(const uint4*)&Qhp[r * 64 + c];
        *(uint4*)&QL[r * FSTR + c] = *(const uint4*)&Qlp[r * 64 + c];
    }

    float m_i[4], l_i[4];     // [mt*2+ih]
    float o[2][8][4];
    #pragma unroll
    for (int t = 0; t < 4; t++) { m_i[t] = -1e30f; l_i[t] = 0.f; }
    #pragma unroll
    for (int mt = 0; mt < 2; mt++)
        #pragma unroll
        for (int ot = 0; ot < 8; ot++)
            #pragma unroll
            for (int q = 0; q < 4; q++) o[mt][ot][q] = 0.f;

    const int qtr = qt * 128;
    const int nkt = 2 * (qt + 1);

    for (int kt = 0; kt < nkt; kt++) {
        const int kv0 = kt * 64;
        const __nv_bfloat16* Khp = g_Kh + (bh * SEQ + kv0) * HDIM;
        const __nv_bfloat16* Klp = g_Kl + (bh * SEQ + kv0) * HDIM;
        const __nv_bfloat16* Vhp = g_Vh + bh * HDIM * SEQ;  // [hd][s]
        const __nv_bfloat16* Vlp = g_Vl + bh * HDIM * SEQ;

        __syncthreads();   // all warps done reading K/V of previous tile
        // K tile: 64 rows(kv) x 64(hd)
        #pragma unroll
        for (int i = 0; i < 4; i++) {
            int idx = tid + i * 128;
            int r = idx >> 3, c = (idx & 7) * 8;
            *(uint4*)&KH[r * FSTR + c] = *(const uint4*)&Khp[r * 64 + c];
            *(uint4*)&KL[r * FSTR + c] = *(const uint4*)&Klp[r * 64 + c];
        }
        // V tile transposed: 64 rows(hd) x 64(kv)
        #pragma unroll
        for (int i = 0; i < 4; i++) {
            int idx = tid + i * 128;
            int r = idx >> 3, c = (idx & 7) * 8;
            *(uint4*)&VH[r * FSTR + c] = *(const uint4*)&Vhp[(size_t)r * SEQ + kv0 + c];
            *(uint4*)&VL[r * FSTR + c] = *(const uint4*)&Vlp[(size_t)r * SEQ + kv0 + c];
        }
        __syncthreads();

        // ---- S = Q @ K^T ----
        float s[2][8][4];
        #pragma unroll
        for (int mt = 0; mt < 2; mt++)
            #pragma unroll
            for (int nt = 0; nt < 8; nt++)
                #pragma unroll
                for (int q = 0; q < 4; q++) s[mt][nt][q] = 0.f;

        #pragma unroll
        for (int ks = 0; ks < 4; ks++) {
            int k0 = ks * 16;
            uint32_t ah[2][4], al[2][4];
            #pragma unroll
            for (int mt = 0; mt < 2; mt++) {
                int r = wid * 32 + mt * 16 + gid;
                ah[mt][0] = *(uint32_t*)&QH[(r    ) * FSTR + k0 + tig*2];
                ah[mt][1] = *(uint32_t*)&QH[(r + 8) * FSTR + k0 + tig*2];
                ah[mt][2] = *(uint32_t*)&QH[(r    ) * FSTR + k0 + tig*2 + 8];
                ah[mt][3] = *(uint32_t*)&QH[(r + 8) * FSTR + k0 + tig*2 + 8];
                al[mt][0] = *(uint32_t*)&QL[(r    ) * FSTR + k0 + tig*2];
                al[mt][1] = *(uint32_t*)&QL[(r + 8) * FSTR + k0 + tig*2];
                al[mt][2] = *(uint32_t*)&QL[(r    ) * FSTR + k0 + tig*2 + 8];
                al[mt][3] = *(uint32_t*)&QL[(r + 8) * FSTR + k0 + tig*2 + 8];
            }
            uint32_t bhf[8][2], blf[8][2];
            #pragma unroll
            for (int nt = 0; nt < 8; nt++) {
                int rn = nt * 8 + gid;
                bhf[nt][0] = *(uint32_t*)&KH[rn * FSTR + k0 + tig*2];
                bhf[nt][1] = *(uint32_t*)&KH[rn * FSTR + k0 + tig*2 + 8];
                blf[nt][0] = *(uint32_t*)&KL[rn * FSTR + k0 + tig*2];
                blf[nt][1] = *(uint32_t*)&KL[rn * FSTR + k0 + tig*2 + 8];
            }
            #pragma unroll
            for (int mt = 0; mt < 2; mt++)
                #pragma unroll
                for (int nt = 0; nt < 8; nt++) {
                    mma16816(s[mt][nt], ah[mt], bhf[nt]);
                    mma16816(s[mt][nt], ah[mt], blf[nt]);
                    mma16816(s[mt][nt], al[mt], bhf[nt]);
                }
        }

        // ---- causal mask ----
        if (kt >= 2 * qt) {
            #pragma unroll
            for (int mt = 0; mt < 2; mt++) {
                int row0 = qtr + wid * 32 + mt * 16 + gid;
                #pragma unroll
                for (int nt = 0; nt < 8; nt++) {
                    int colb = kv0 + nt * 8 + tig * 2;
                    if (colb     > row0    ) s[mt][nt][0] = -1e30f;
                    if (colb + 1 > row0    ) s[mt][nt][1] = -1e30f;
                    if (colb     > row0 + 8) s[mt][nt][2] = -1e30f;
                    if (colb + 1 > row0 + 8) s[mt][nt][3] = -1e30f;
                }
            }
        }

        // ---- online softmax (rows owned by 4-lane groups) ----
        #pragma unroll
        for (int mt = 0; mt < 2; mt++) {
            #pragma unroll
            for (int ih = 0; ih < 2; ih++) {
                int si = mt * 2 + ih;
                float mx = m_i[si];
                #pragma unroll
                for (int nt = 0; nt < 8; nt++)
                    mx = fmaxf(mx, fmaxf(s[mt][nt][ih*2], s[mt][nt][ih*2+1]));
                mx = fmaxf(mx, __shfl_xor_sync(0xffffffffu, mx, 1));
                mx = fmaxf(mx, __shfl_xor_sync(0xffffffffu, mx, 2));
                float corr = __expf(m_i[si] - mx);
                float sum = 0.f;
                #pragma unroll
                for (int nt = 0; nt < 8; nt++) {
                    float p0 = __expf(s[mt][nt][ih*2]   - mx);
                    float p1 = __expf(s[mt][nt][ih*2+1] - mx);
                    s[mt][nt][ih*2]   = p0;
                    s[mt][nt][ih*2+1] = p1;
                    sum += p0 + p1;
                }
                sum += __shfl_xor_sync(0xffffffffu, sum, 1);
                sum += __shfl_xor_sync(0xffffffffu, sum, 2);
                l_i[si] = l_i[si] * corr + sum;
                m_i[si] = mx;
                #pragma unroll
                for (int ot = 0; ot < 8; ot++) {
                    o[mt][ot][ih*2]   *= corr;
                    o[mt][ot][ih*2+1] *= corr;
                }
            }
        }

        // ---- O += P @ V ----
        #pragma unroll
        for (int ks = 0; ks < 4; ks++) {
            uint32_t pah[2][4], pal[2][4];
            #pragma unroll
            for (int mt = 0; mt < 2; mt++) {
                packsplit(s[mt][2*ks  ][0], s[mt][2*ks  ][1], pah[mt][0], pal[mt][0]);
                packsplit(s[mt][2*ks  ][2], s[mt][2*ks  ][3], pah[mt][1], pal[mt][1]);
                packsplit(s[mt][2*ks+1][0], s[mt][2*ks+1][1], pah[mt][2], pal[mt][2]);
                packsplit(s[mt][2*ks+1][2], s[mt][2*ks+1][3], pah[mt][3], pal[mt][3]);
            }
            uint32_t vbh[8][2], vbl[8][2];
            #pragma unroll
            for (int ot = 0; ot < 8; ot++) {
                int rn = ot * 8 + gid;        // hd row
                vbh[ot][0] = *(uint32_t*)&VH[rn * FSTR + ks*16 + tig*2];
                vbh[ot][1] = *(uint32_t*)&VH[rn * FSTR + ks*16 + tig*2 + 8];
                vbl[ot][0] = *(uint32_t*)&VL[rn * FSTR + ks*16 + tig*2];
                vbl[ot][1] = *(uint32_t*)&VL[rn * FSTR + ks*16 + tig*2 + 8];
            }
            #pragma unroll
            for (int mt = 0; mt < 2; mt++)
                #pragma unroll
                for (int ot = 0; ot < 8; ot++) {
                    mma16816(o[mt][ot], pah[mt], vbh[ot]);
                    mma16816(o[mt][ot], pal[mt], vbh[ot]);
                    mma16816(o[mt][ot], pah[mt], vbl[ot]);
                }
        }
    }

    // ---- epilogue: normalize, write fp32 ----
    float* Yb = g_Y + ((size_t)b * SEQ + qtr) * DIM + head * HDIM;
    #pragma unroll
    for (int mt = 0; mt < 2; mt++) {
        #pragma unroll
        for (int ih = 0; ih < 2; ih++) {
            float inv = 1.0f / l_i[mt * 2 + ih];
            int rl = wid * 32 + mt * 16 + gid + ih * 8;
            #pragma unroll
            for (int ot = 0; ot < 8; ot++) {
                float2 o2 = { o[mt][ot][ih*2] * inv, o[mt][ot][ih*2+1] * inv };
                *(float2*)&Yb[(size_t)rl * DIM + ot * 8 + tig * 2] = o2;
            }
        }
    }
}

// ---------------------------------------------------------------------------
extern "C" void kernel_launch(void* const* d_in, const int* in_sizes, int n_in,
                              void* d_out, int out_size)
{
    const float* x    = (const float*)d_in[0];   // [2,4096,512]
    const float* Wqkv = (const float*)d_in[1];   // [1536,512]
    const float* bqkv = (const float*)d_in[2];   // [1536]
    const float* Wo   = (const float*)d_in[3];   // [512,512]
    const float* bo   = (const float*)d_in[4];   // [512]
    float* out = (float*)d_out;                  // [2,4096,512]

    void* yptr = nullptr;
    cudaGetSymbolAddress(&yptr, g_Y);

    cudaFuncSetAttribute(flash_mma, cudaFuncAttributeMaxDynamicSharedMemorySize, FL_SMEM);

    const int M = BSZ * SEQ;   // 8192

    gemm_mma<1><<<dim3(12, 64), 256>>>(x, Wqkv, bqkv, nullptr, M, 3 * DIM, DIM);
    flash_mma<<<dim3(SEQ / 128, NH, BSZ), 128, FL_SMEM>>>();
    gemm_mma<0><<<dim3(4, 64), 256>>>((const float*)yptr, Wo, bo, out, M, DIM, DIM);
}